// round 1
// baseline (speedup 1.0000x reference)
#include <cuda_runtime.h>

#define B_ 64
#define J_ 25
#define V_ 50000
#define VT 256          // vertices per block (= threads)
#define NB 8            // batches per block
#define NPAIR (NB/2)

// Scratch (device globals; no allocation allowed)
__device__ float g_L[B_*J_*12];   // per-(b,j) local affine (3x4 row-major)
__device__ float g_T[B_*J_*12];   // per-(b,j) skinning transform (3x4 row-major)

// ---------------------------------------------------------------------------
// Kernel A1: local = (local_pose with t += skel_corr) @ euler2mat(joint_euler)
// ---------------------------------------------------------------------------
__global__ void locals_kernel(const float* __restrict__ je,
                              const float* __restrict__ lp,
                              const float* __restrict__ sc) {
    int idx = blockIdx.x * blockDim.x + threadIdx.x;
    if (idx >= B_ * J_) return;
    int j = idx % J_;
    float ex = je[idx*3+0], ey = je[idx*3+1], ez = je[idx*3+2];
    float sx, cx, sy, cy, sz, cz;
    sincosf(ex, &sx, &cx);
    sincosf(ey, &sy, &cy);
    sincosf(ez, &sz, &cz);
    // euler2mat4 rows (rotation part)
    float R00 = cz*cy, R01 = cz*sy*sx - sz*cx, R02 = cz*sy*cx + sz*sx;
    float R10 = sz*cy, R11 = sz*sy*sx + cz*cx, R12 = sz*sy*cx - cz*sx;
    float R20 = -sy,   R21 = cy*sx,            R22 = cy*cx;
    const float* L0 = lp + j*16;
    float* out = g_L + idx*12;
    #pragma unroll
    for (int r = 0; r < 3; ++r) {
        float a0 = L0[r*4+0], a1 = L0[r*4+1], a2 = L0[r*4+2];
        // local[r][c] = sum_k Lp[r][k] * R[k][c]; translation col passes through
        out[r*4+0] = a0*R00 + a1*R10 + a2*R20;
        out[r*4+1] = a0*R01 + a1*R11 + a2*R21;
        out[r*4+2] = a0*R02 + a1*R12 + a2*R22;
        out[r*4+3] = L0[r*4+3] + sc[j*3+r];
    }
}

// ---------------------------------------------------------------------------
// Kernel A2: FK chain per batch. Thread = (b, row r). Rows of G compose
// independently: G[j] row r = (G[parent] row r) o L[j].
// Also emits T[b,j] = G[b,j] @ global_pose_inv[j] and joint_out.
// ---------------------------------------------------------------------------
__global__ void chain_kernel(const float* __restrict__ gpi,
                             const int* __restrict__ parents,
                             float* __restrict__ joint_out) {
    int t = threadIdx.x;
    if (t >= B_ * 3) return;
    int b = t / 3, r = t % 3;
    float Grow[J_][4];
    float pr0 = 0.f, pr1 = 0.f, pr2 = 0.f, pr3 = 0.f;
    int prevj = -2;
    for (int j = 0; j < J_; ++j) {
        int pj = parents[j];
        float g0, g1, g2, g3;
        if (pj < 0) {
            g0 = (r == 0) ? 1.f : 0.f;
            g1 = (r == 1) ? 1.f : 0.f;
            g2 = (r == 2) ? 1.f : 0.f;
            g3 = 0.f;
        } else {
            float p0, p1, p2, p3;
            if (pj == prevj) { p0 = pr0; p1 = pr1; p2 = pr2; p3 = pr3; }
            else { p0 = Grow[pj][0]; p1 = Grow[pj][1]; p2 = Grow[pj][2]; p3 = Grow[pj][3]; }
            const float* L = g_L + (b*J_ + j) * 12;
            g0 = p0*L[0] + p1*L[4] + p2*L[8];
            g1 = p0*L[1] + p1*L[5] + p2*L[9];
            g2 = p0*L[2] + p1*L[6] + p2*L[10];
            g3 = p0*L[3] + p1*L[7] + p2*L[11] + p3;
        }
        Grow[j][0] = g0; Grow[j][1] = g1; Grow[j][2] = g2; Grow[j][3] = g3;
        pr0 = g0; pr1 = g1; pr2 = g2; pr3 = g3; prevj = j;

        const float* P = gpi + j*16;
        float* T = g_T + (b*J_ + j) * 12 + r*4;
        T[0] = g0*P[0] + g1*P[4] + g2*P[8];
        T[1] = g0*P[1] + g1*P[5] + g2*P[9];
        T[2] = g0*P[2] + g1*P[6] + g2*P[10];
        T[3] = g0*P[3] + g1*P[7] + g2*P[11] + g3;
        joint_out[(b*J_ + j)*3 + r] = g3;
    }
}

// ---------------------------------------------------------------------------
// f32x2 packed helpers (sm_100+)
// ---------------------------------------------------------------------------
__device__ __forceinline__ unsigned long long pack2(float lo, float hi) {
    unsigned long long d;
    asm("mov.b64 %0, {%1, %2};" : "=l"(d)
        : "r"(__float_as_uint(lo)), "r"(__float_as_uint(hi)));
    return d;
}
__device__ __forceinline__ void unpack2(unsigned long long s, float& lo, float& hi) {
    unsigned int a, b;
    asm("mov.b64 {%0, %1}, %2;" : "=r"(a), "=r"(b) : "l"(s));
    lo = __uint_as_float(a); hi = __uint_as_float(b);
}
__device__ __forceinline__ void fma2acc(unsigned long long& d,
                                        unsigned long long a,
                                        unsigned long long b) {
    asm("fma.rn.f32x2 %0, %1, %2, %0;" : "+l"(d) : "l"(a), "l"(b));
}
__device__ __forceinline__ unsigned long long fma2(unsigned long long a,
                                                   unsigned long long b,
                                                   unsigned long long c) {
    unsigned long long d;
    asm("fma.rn.f32x2 %0, %1, %2, %3;" : "=l"(d) : "l"(a), "l"(b), "l"(c));
    return d;
}

// ---------------------------------------------------------------------------
// Kernel B: skinning. Block = 256-vertex tile x 8 batches (4 batch pairs).
// Weights staged coalesced into smem, held in registers across batches.
// T for each batch pair staged interleaved as float2 -> packed fma.f32x2
// processes both batches per instruction (halves FMA-pipe load).
// ---------------------------------------------------------------------------
__global__ __launch_bounds__(VT, 2)
void skin_kernel(const float* __restrict__ vtx,
                 const float* __restrict__ W,
                 const float* __restrict__ pc,
                 const float* __restrict__ ic,
                 float* __restrict__ mesh_out) {
    __shared__ float ws[VT * J_];
    __shared__ __align__(16) float2 Ts[NPAIR * J_ * 12];

    int tid = threadIdx.x;
    int v0 = blockIdx.x * VT;
    int b0base = blockIdx.y * NB;
    int nv = min(VT, V_ - v0);

    // Stage weights for this vertex tile (fully coalesced: contiguous region)
    int nW = nv * J_;
    for (int i = tid; i < nW; i += VT)
        ws[i] = W[(size_t)v0 * J_ + i];

    // Stage T for NB batches, interleaved per batch pair: Ts[(p*J+j)*12+k] =
    // {T[b0base+2p, j, k], T[b0base+2p+1, j, k]}
    for (int i = tid; i < NPAIR * J_ * 12; i += VT) {
        int p = i / (J_ * 12);
        int rem = i - p * (J_ * 12);
        int b0 = b0base + 2 * p;
        Ts[i] = make_float2(g_T[b0 * J_ * 12 + rem],
                            g_T[(b0 + 1) * J_ * 12 + rem]);
    }
    __syncthreads();

    if (tid >= nv) return;
    int v = v0 + tid;

    float wreg[J_];
    #pragma unroll
    for (int j = 0; j < J_; ++j) wreg[j] = ws[tid * J_ + j];   // stride 25: conflict-free

    float vx = vtx[v*3+0], vy = vtx[v*3+1], vz = vtx[v*3+2];

    #pragma unroll 1
    for (int p = 0; p < NPAIR; ++p) {
        int b0 = b0base + 2 * p;
        size_t o0 = ((size_t)b0 * V_ + v) * 3;
        size_t o1 = o0 + (size_t)V_ * 3;

        float p0x = vx + pc[o0+0] + ic[o0+0];
        float p0y = vy + pc[o0+1] + ic[o0+1];
        float p0z = vz + pc[o0+2] + ic[o0+2];
        float p1x = vx + pc[o1+0] + ic[o1+0];
        float p1y = vy + pc[o1+1] + ic[o1+1];
        float p1z = vz + pc[o1+2] + ic[o1+2];

        unsigned long long M2[12];
        #pragma unroll
        for (int k = 0; k < 12; ++k) M2[k] = 0ull;

        const ulonglong2* tbase =
            reinterpret_cast<const ulonglong2*>(Ts + p * J_ * 12);
        #pragma unroll
        for (int j = 0; j < J_; ++j) {
            unsigned long long w2 = pack2(wreg[j], wreg[j]);
            const ulonglong2* trow = tbase + j * 6;   // 12 float2 = 6 x 16B
            #pragma unroll
            for (int m = 0; m < 6; ++m) {
                ulonglong2 q = trow[m];
                fma2acc(M2[2*m],     q.x, w2);
                fma2acc(M2[2*m + 1], q.y, w2);
            }
        }

        unsigned long long ppx = pack2(p0x, p1x);
        unsigned long long ppy = pack2(p0y, p1y);
        unsigned long long ppz = pack2(p0z, p1z);
        #pragma unroll
        for (int r = 0; r < 3; ++r) {
            unsigned long long o = M2[r*4 + 3];
            o = fma2(M2[r*4 + 0], ppx, o);
            o = fma2(M2[r*4 + 1], ppy, o);
            o = fma2(M2[r*4 + 2], ppz, o);
            float a, bb; unpack2(o, a, bb);
            mesh_out[o0 + r] = a;
            mesh_out[o1 + r] = bb;
        }
    }
}

// ---------------------------------------------------------------------------
extern "C" void kernel_launch(void* const* d_in, const int* in_sizes, int n_in,
                              void* d_out, int out_size) {
    const float* joint_euler = (const float*)d_in[0];
    const float* vtx         = (const float*)d_in[1];
    const float* W           = (const float*)d_in[2];
    const float* local_pose  = (const float*)d_in[3];
    const float* gpi         = (const float*)d_in[4];
    const float* sc          = (const float*)d_in[5];
    const float* pc          = (const float*)d_in[6];
    const float* ic          = (const float*)d_in[7];
    const int*   parents     = (const int*)d_in[8];
    float* out = (float*)d_out;

    locals_kernel<<<(B_*J_ + 255) / 256, 256>>>(joint_euler, local_pose, sc);
    chain_kernel<<<1, 192>>>(gpi, parents, out);            // writes joint_out
    dim3 grid((V_ + VT - 1) / VT, B_ / NB);
    skin_kernel<<<grid, VT>>>(vtx, W, pc, ic, out + B_*J_*3);
}